// round 1
// baseline (speedup 1.0000x reference)
#include <cuda_runtime.h>
#include <math.h>

// Problem constants
#define B_  4
#define L_  2048
#define D_  1024
#define H_  16
#define DH_ 64

// Scratch (device globals: allocation-free per harness rules)
__device__ float g_qkv[B_ * L_ * 3 * D_];   // [B*L, 3072]  (96 MB)
__device__ float g_attn[B_ * L_ * D_];      // [B*L, 1024]  (32 MB)

// ---------------------------------------------------------------------------
// SGEMM (NT): C[m,n] = sum_k A[m,k] * Bm[n,k]
// A: MxK row-major, Bm: NxK row-major, C: MxN row-major.
// M,N multiples of 128; K multiple of 16.
// Block tile 128x128, K-tile 16, 256 threads, 8x8 per thread (split 4+4).
// ---------------------------------------------------------------------------
__global__ __launch_bounds__(256, 2)
void sgemm_nt(const float* __restrict__ A, const float* __restrict__ Bm,
              float* __restrict__ C, int M, int N, int K)
{
    __shared__ float As[16][132];
    __shared__ float Bs[16][132];

    const int tid = threadIdx.x;
    const int ty = tid >> 4;     // 0..15
    const int tx = tid & 15;     // 0..15

    const size_t arow0 = (size_t)blockIdx.y * 128;
    const size_t brow0 = (size_t)blockIdx.x * 128;
    const float* Ab = A + arow0 * (size_t)K;
    const float* Bb = Bm + brow0 * (size_t)K;

    float acc[8][8];
#pragma unroll
    for (int i = 0; i < 8; i++)
#pragma unroll
        for (int j = 0; j < 8; j++) acc[i][j] = 0.f;

    for (int k0 = 0; k0 < K; k0 += 16) {
        // Load A-tile and B-tile (each 128x16) transposed into smem.
#pragma unroll
        for (int i = 0; i < 2; i++) {
            int v   = tid + i * 256;         // [0,512)
            int row = v >> 2;                // [0,128)
            int c4  = (v & 3) << 2;          // {0,4,8,12}
            float4 a = *(const float4*)(Ab + (size_t)row * K + k0 + c4);
            As[c4 + 0][row] = a.x; As[c4 + 1][row] = a.y;
            As[c4 + 2][row] = a.z; As[c4 + 3][row] = a.w;
            float4 b = *(const float4*)(Bb + (size_t)row * K + k0 + c4);
            Bs[c4 + 0][row] = b.x; Bs[c4 + 1][row] = b.y;
            Bs[c4 + 2][row] = b.z; Bs[c4 + 3][row] = b.w;
        }
        __syncthreads();

#pragma unroll
        for (int kk = 0; kk < 16; kk++) {
            float4 a0 = *(const float4*)&As[kk][ty * 4];
            float4 a1 = *(const float4*)&As[kk][64 + ty * 4];
            float4 b0 = *(const float4*)&Bs[kk][tx * 4];
            float4 b1 = *(const float4*)&Bs[kk][64 + tx * 4];
            float a[8] = {a0.x, a0.y, a0.z, a0.w, a1.x, a1.y, a1.z, a1.w};
            float b[8] = {b0.x, b0.y, b0.z, b0.w, b1.x, b1.y, b1.z, b1.w};
#pragma unroll
            for (int i = 0; i < 8; i++)
#pragma unroll
                for (int j = 0; j < 8; j++)
                    acc[i][j] += a[i] * b[j];
        }
        __syncthreads();
    }

    // Store: rows {ty*4+ii, 64+ty*4+ii}, cols {tx*4.., 64+tx*4..}
#pragma unroll
    for (int ih = 0; ih < 2; ih++) {
#pragma unroll
        for (int ii = 0; ii < 4; ii++) {
            int i = ih * 4 + ii;
            size_t mrow = arow0 + ih * 64 + ty * 4 + ii;
            float* cp = C + mrow * (size_t)N + brow0;
            *(float4*)(cp + tx * 4) =
                make_float4(acc[i][0], acc[i][1], acc[i][2], acc[i][3]);
            *(float4*)(cp + 64 + tx * 4) =
                make_float4(acc[i][4], acc[i][5], acc[i][6], acc[i][7]);
        }
    }
}

// ---------------------------------------------------------------------------
// Flash attention over precomputed qkv buffer.
// qkv layout: [B*L, 3*1024]; feature n = qkvIdx*1024 + h*64 + dh.
// Block = (q-tile of 64, h, b). 256 threads. Online softmax.
// Output: g_attn[(b*L+q)*1024 + h*64 + d]  (i.e. already [B,L,H,DH] merged).
// ---------------------------------------------------------------------------
#define ATTN_SMEM_FLOATS (64*65 + 64*65 + 64*68 + 64*68 + 64)
#define ATTN_SMEM_BYTES  (ATTN_SMEM_FLOATS * 4)

__global__ __launch_bounds__(256)
void attn_kernel(const float* __restrict__ qkv, float* __restrict__ out)
{
    extern __shared__ float sm[];
    float* Qs = sm;                 // [64][65]  (pre-scaled by 1/sqrt(DH))
    float* Ks = Qs + 64 * 65;       // [64][65]
    float* Vs = Ks + 64 * 65;       // [64][68]
    float* Ss = Vs + 64 * 68;       // [64][68]
    float* Cr = Ss + 64 * 68;       // [64] per-row corr / 1/l

    const int tid = threadIdx.x;
    const int qt = blockIdx.x, h = blockIdx.y, b = blockIdx.z;
    const int q0 = qt * 64;
    const float scale = 0.125f;     // 1/sqrt(64)

    const int tr = tid >> 4, tc = tid & 15;   // GEMM-phase mapping (16x16)
    const int r  = tid >> 2, p  = tid & 3;    // softmax-phase mapping (64x4)

    // Load Q tile (scaled)
#pragma unroll
    for (int i = 0; i < 4; i++) {
        int v = tid + i * 256;              // [0,1024)
        int row = v >> 4; int c = (v & 15) << 2;
        const float* gp = qkv + ((size_t)(b * L_ + q0 + row)) * 3072 + h * 64 + c;
        float4 x4 = *(const float4*)gp;
        float* qd = &Qs[row * 65 + c];
        qd[0] = x4.x * scale; qd[1] = x4.y * scale;
        qd[2] = x4.z * scale; qd[3] = x4.w * scale;
    }

    float m = -1e30f, l = 0.f;
    float o[16];
#pragma unroll
    for (int i = 0; i < 16; i++) o[i] = 0.f;

    __syncthreads();

    for (int kt = 0; kt < 32; kt++) {
        // Load K,V tiles
#pragma unroll
        for (int i = 0; i < 4; i++) {
            int v = tid + i * 256;
            int row = v >> 4; int c = (v & 15) << 2;
            size_t gb = ((size_t)(b * L_ + kt * 64 + row)) * 3072 + h * 64 + c;
            float4 k4 = *(const float4*)(qkv + gb + 1024);
            float* kd = &Ks[row * 65 + c];
            kd[0] = k4.x; kd[1] = k4.y; kd[2] = k4.z; kd[3] = k4.w;
            float4 v4 = *(const float4*)(qkv + gb + 2048);
            *(float4*)&Vs[row * 68 + c] = v4;
        }
        __syncthreads();

        // Phase 1: S = Q K^T, 4x4 per thread
        float s[4][4];
#pragma unroll
        for (int i = 0; i < 4; i++)
#pragma unroll
            for (int j = 0; j < 4; j++) s[i][j] = 0.f;
#pragma unroll 8
        for (int k = 0; k < 64; k++) {
            float a[4], bb[4];
#pragma unroll
            for (int i = 0; i < 4; i++) a[i] = Qs[(tr * 4 + i) * 65 + k];
#pragma unroll
            for (int j = 0; j < 4; j++) bb[j] = Ks[(tc * 4 + j) * 65 + k];
#pragma unroll
            for (int i = 0; i < 4; i++)
#pragma unroll
                for (int j = 0; j < 4; j++)
                    s[i][j] += a[i] * bb[j];
        }
#pragma unroll
        for (int i = 0; i < 4; i++)
            *(float4*)&Ss[(tr * 4 + i) * 68 + tc * 4] =
                make_float4(s[i][0], s[i][1], s[i][2], s[i][3]);
        __syncthreads();

        // Phase 2A: per-row online softmax update (4 threads/row)
        float sv[16];
        float tmax = -1e30f;
#pragma unroll
        for (int jj = 0; jj < 16; jj++) {
            sv[jj] = Ss[r * 68 + p * 16 + jj];
            tmax = fmaxf(tmax, sv[jj]);
        }
        tmax = fmaxf(tmax, __shfl_xor_sync(0xffffffffu, tmax, 1));
        tmax = fmaxf(tmax, __shfl_xor_sync(0xffffffffu, tmax, 2));
        float mn = fmaxf(m, tmax);
        float corr = __expf(m - mn);
        float ps = 0.f;
#pragma unroll
        for (int jj = 0; jj < 16; jj++) {
            float e = __expf(sv[jj] - mn);
            Ss[r * 68 + p * 16 + jj] = e;
            ps += e;
        }
        ps += __shfl_xor_sync(0xffffffffu, ps, 1);
        ps += __shfl_xor_sync(0xffffffffu, ps, 2);
        l = l * corr + ps;
        m = mn;
        if (p == 0) Cr[r] = corr;
        __syncthreads();

        // Phase 2B: O = O*corr_row + P V  (thread (tr,tc): rows tr*4+i, cols tc*4+j)
        float cf[4];
#pragma unroll
        for (int i = 0; i < 4; i++) cf[i] = Cr[tr * 4 + i];
#pragma unroll
        for (int i = 0; i < 4; i++)
#pragma unroll
            for (int j = 0; j < 4; j++) o[i * 4 + j] *= cf[i];
#pragma unroll 8
        for (int k = 0; k < 64; k++) {
            float a[4];
#pragma unroll
            for (int i = 0; i < 4; i++) a[i] = Ss[(tr * 4 + i) * 68 + k];
            float4 v4 = *(const float4*)&Vs[k * 68 + tc * 4];
#pragma unroll
            for (int i = 0; i < 4; i++) {
                o[i * 4 + 0] += a[i] * v4.x;
                o[i * 4 + 1] += a[i] * v4.y;
                o[i * 4 + 2] += a[i] * v4.z;
                o[i * 4 + 3] += a[i] * v4.w;
            }
        }
        __syncthreads();
    }

    // Finalize: divide by l, write [B,L,H*DH]
    if (p == 0) Cr[r] = 1.f / l;
    __syncthreads();
#pragma unroll
    for (int i = 0; i < 4; i++) {
        float linv = Cr[tr * 4 + i];
        float4 ov = make_float4(o[i * 4 + 0] * linv, o[i * 4 + 1] * linv,
                                o[i * 4 + 2] * linv, o[i * 4 + 3] * linv);
        *(float4*)(out + ((size_t)(b * L_ + q0 + tr * 4 + i)) * 1024 + h * 64 + tc * 4) = ov;
    }
}

// ---------------------------------------------------------------------------
extern "C" void kernel_launch(void* const* d_in, const int* in_sizes, int n_in,
                              void* d_out, int out_size)
{
    (void)in_sizes; (void)n_in; (void)out_size;
    const float* x      = (const float*)d_in[0];   // [B,L,D]
    const float* w_qkv  = (const float*)d_in[1];   // [3D,D]
    const float* w_proj = (const float*)d_in[2];   // [D,D]
    float* out = (float*)d_out;                    // [B,L,D]

    float* qkvp = nullptr;
    float* attnp = nullptr;
    cudaGetSymbolAddress((void**)&qkvp, g_qkv);
    cudaGetSymbolAddress((void**)&attnp, g_attn);

    const int M = B_ * L_;  // 8192

    // 1) QKV GEMM: [8192,1024] x [3072,1024]^T -> [8192,3072]
    {
        dim3 grid(3 * D_ / 128, M / 128);
        sgemm_nt<<<grid, 256>>>(x, w_qkv, qkvp, M, 3 * D_, D_);
    }

    // 2) Flash attention
    {
        cudaFuncSetAttribute(attn_kernel,
                             cudaFuncAttributeMaxDynamicSharedMemorySize,
                             ATTN_SMEM_BYTES);
        dim3 grid(L_ / 64, H_, B_);
        attn_kernel<<<grid, 256, ATTN_SMEM_BYTES>>>(qkvp, attnp);
    }

    // 3) Output projection: [8192,1024] x [1024,1024]^T -> [8192,1024]
    {
        dim3 grid(D_ / 128, M / 128);
        sgemm_nt<<<grid, 256>>>(attnp, w_proj, out, M, D_, D_);
    }
}

// round 2
// speedup vs baseline: 1.0002x; 1.0002x over previous
#include <cuda_runtime.h>
#include <math.h>

// Problem constants
#define B_  4
#define L_  2048
#define D_  1024
#define H_  16
#define DH_ 64

// Scratch (device globals: allocation-free per harness rules)
__device__ float g_qkv[B_ * L_ * 3 * D_];   // [B*L, 3072]  (96 MB)
__device__ float g_attn[B_ * L_ * D_];      // [B*L, 1024]  (32 MB)

// ---------------------------------------------------------------------------
// SGEMM (NT): C[m,n] = sum_k A[m,k] * Bm[n,k]
// A: MxK row-major, Bm: NxK row-major, C: MxN row-major.
// M,N multiples of 128; K multiple of 16.
// Block tile 128x128, K-tile 16, 256 threads, 8x8 per thread (split 4+4).
// ---------------------------------------------------------------------------
__global__ __launch_bounds__(256, 2)
void sgemm_nt(const float* __restrict__ A, const float* __restrict__ Bm,
              float* __restrict__ C, int M, int N, int K)
{
    __shared__ float As[16][132];
    __shared__ float Bs[16][132];

    const int tid = threadIdx.x;
    const int ty = tid >> 4;     // 0..15
    const int tx = tid & 15;     // 0..15

    const size_t arow0 = (size_t)blockIdx.y * 128;
    const size_t brow0 = (size_t)blockIdx.x * 128;
    const float* Ab = A + arow0 * (size_t)K;
    const float* Bb = Bm + brow0 * (size_t)K;

    float acc[8][8];
#pragma unroll
    for (int i = 0; i < 8; i++)
#pragma unroll
        for (int j = 0; j < 8; j++) acc[i][j] = 0.f;

    for (int k0 = 0; k0 < K; k0 += 16) {
        // Load A-tile and B-tile (each 128x16) transposed into smem.
#pragma unroll
        for (int i = 0; i < 2; i++) {
            int v   = tid + i * 256;         // [0,512)
            int row = v >> 2;                // [0,128)
            int c4  = (v & 3) << 2;          // {0,4,8,12}
            float4 a = *(const float4*)(Ab + (size_t)row * K + k0 + c4);
            As[c4 + 0][row] = a.x; As[c4 + 1][row] = a.y;
            As[c4 + 2][row] = a.z; As[c4 + 3][row] = a.w;
            float4 b = *(const float4*)(Bb + (size_t)row * K + k0 + c4);
            Bs[c4 + 0][row] = b.x; Bs[c4 + 1][row] = b.y;
            Bs[c4 + 2][row] = b.z; Bs[c4 + 3][row] = b.w;
        }
        __syncthreads();

#pragma unroll
        for (int kk = 0; kk < 16; kk++) {
            float4 a0 = *(const float4*)&As[kk][ty * 4];
            float4 a1 = *(const float4*)&As[kk][64 + ty * 4];
            float4 b0 = *(const float4*)&Bs[kk][tx * 4];
            float4 b1 = *(const float4*)&Bs[kk][64 + tx * 4];
            float a[8] = {a0.x, a0.y, a0.z, a0.w, a1.x, a1.y, a1.z, a1.w};
            float b[8] = {b0.x, b0.y, b0.z, b0.w, b1.x, b1.y, b1.z, b1.w};
#pragma unroll
            for (int i = 0; i < 8; i++)
#pragma unroll
                for (int j = 0; j < 8; j++)
                    acc[i][j] += a[i] * b[j];
        }
        __syncthreads();
    }

    // Store: rows {ty*4+ii, 64+ty*4+ii}, cols {tx*4.., 64+tx*4..}
#pragma unroll
    for (int ih = 0; ih < 2; ih++) {
#pragma unroll
        for (int ii = 0; ii < 4; ii++) {
            int i = ih * 4 + ii;
            size_t mrow = arow0 + ih * 64 + ty * 4 + ii;
            float* cp = C + mrow * (size_t)N + brow0;
            *(float4*)(cp + tx * 4) =
                make_float4(acc[i][0], acc[i][1], acc[i][2], acc[i][3]);
            *(float4*)(cp + 64 + tx * 4) =
                make_float4(acc[i][4], acc[i][5], acc[i][6], acc[i][7]);
        }
    }
}

// ---------------------------------------------------------------------------
// Flash attention over precomputed qkv buffer.
// qkv layout: [B*L, 3*1024]; feature n = qkvIdx*1024 + h*64 + dh.
// Block = (q-tile of 64, h, b). 256 threads. Online softmax.
// Output: g_attn[(b*L+q)*1024 + h*64 + d]  (i.e. already [B,L,H,DH] merged).
// ---------------------------------------------------------------------------
#define ATTN_SMEM_FLOATS (64*65 + 64*65 + 64*68 + 64*68 + 64)
#define ATTN_SMEM_BYTES  (ATTN_SMEM_FLOATS * 4)

__global__ __launch_bounds__(256)
void attn_kernel(const float* __restrict__ qkv, float* __restrict__ out)
{
    extern __shared__ float sm[];
    float* Qs = sm;                 // [64][65]  (pre-scaled by 1/sqrt(DH))
    float* Ks = Qs + 64 * 65;       // [64][65]
    float* Vs = Ks + 64 * 65;       // [64][68]
    float* Ss = Vs + 64 * 68;       // [64][68]
    float* Cr = Ss + 64 * 68;       // [64] per-row corr / 1/l

    const int tid = threadIdx.x;
    const int qt = blockIdx.x, h = blockIdx.y, b = blockIdx.z;
    const int q0 = qt * 64;
    const float scale = 0.125f;     // 1/sqrt(64)

    const int tr = tid >> 4, tc = tid & 15;   // GEMM-phase mapping (16x16)
    const int r  = tid >> 2, p  = tid & 3;    // softmax-phase mapping (64x4)

    // Load Q tile (scaled)
#pragma unroll
    for (int i = 0; i < 4; i++) {
        int v = tid + i * 256;              // [0,1024)
        int row = v >> 4; int c = (v & 15) << 2;
        const float* gp = qkv + ((size_t)(b * L_ + q0 + row)) * 3072 + h * 64 + c;
        float4 x4 = *(const float4*)gp;
        float* qd = &Qs[row * 65 + c];
        qd[0] = x4.x * scale; qd[1] = x4.y * scale;
        qd[2] = x4.z * scale; qd[3] = x4.w * scale;
    }

    float m = -1e30f, l = 0.f;
    float o[16];
#pragma unroll
    for (int i = 0; i < 16; i++) o[i] = 0.f;

    __syncthreads();

    for (int kt = 0; kt < 32; kt++) {
        // Load K,V tiles
#pragma unroll
        for (int i = 0; i < 4; i++) {
            int v = tid + i * 256;
            int row = v >> 4; int c = (v & 15) << 2;
            size_t gb = ((size_t)(b * L_ + kt * 64 + row)) * 3072 + h * 64 + c;
            float4 k4 = *(const float4*)(qkv + gb + 1024);
            float* kd = &Ks[row * 65 + c];
            kd[0] = k4.x; kd[1] = k4.y; kd[2] = k4.z; kd[3] = k4.w;
            float4 v4 = *(const float4*)(qkv + gb + 2048);
            *(float4*)&Vs[row * 68 + c] = v4;
        }
        __syncthreads();

        // Phase 1: S = Q K^T, 4x4 per thread
        float s[4][4];
#pragma unroll
        for (int i = 0; i < 4; i++)
#pragma unroll
            for (int j = 0; j < 4; j++) s[i][j] = 0.f;
#pragma unroll 8
        for (int k = 0; k < 64; k++) {
            float a[4], bb[4];
#pragma unroll
            for (int i = 0; i < 4; i++) a[i] = Qs[(tr * 4 + i) * 65 + k];
#pragma unroll
            for (int j = 0; j < 4; j++) bb[j] = Ks[(tc * 4 + j) * 65 + k];
#pragma unroll
            for (int i = 0; i < 4; i++)
#pragma unroll
                for (int j = 0; j < 4; j++)
                    s[i][j] += a[i] * bb[j];
        }
#pragma unroll
        for (int i = 0; i < 4; i++)
            *(float4*)&Ss[(tr * 4 + i) * 68 + tc * 4] =
                make_float4(s[i][0], s[i][1], s[i][2], s[i][3]);
        __syncthreads();

        // Phase 2A: per-row online softmax update (4 threads/row)
        float sv[16];
        float tmax = -1e30f;
#pragma unroll
        for (int jj = 0; jj < 16; jj++) {
            sv[jj] = Ss[r * 68 + p * 16 + jj];
            tmax = fmaxf(tmax, sv[jj]);
        }
        tmax = fmaxf(tmax, __shfl_xor_sync(0xffffffffu, tmax, 1));
        tmax = fmaxf(tmax, __shfl_xor_sync(0xffffffffu, tmax, 2));
        float mn = fmaxf(m, tmax);
        float corr = __expf(m - mn);
        float ps = 0.f;
#pragma unroll
        for (int jj = 0; jj < 16; jj++) {
            float e = __expf(sv[jj] - mn);
            Ss[r * 68 + p * 16 + jj] = e;
            ps += e;
        }
        ps += __shfl_xor_sync(0xffffffffu, ps, 1);
        ps += __shfl_xor_sync(0xffffffffu, ps, 2);
        l = l * corr + ps;
        m = mn;
        if (p == 0) Cr[r] = corr;
        __syncthreads();

        // Phase 2B: O = O*corr_row + P V  (thread (tr,tc): rows tr*4+i, cols tc*4+j)
        float cf[4];
#pragma unroll
        for (int i = 0; i < 4; i++) cf[i] = Cr[tr * 4 + i];
#pragma unroll
        for (int i = 0; i < 4; i++)
#pragma unroll
            for (int j = 0; j < 4; j++) o[i * 4 + j] *= cf[i];
#pragma unroll 8
        for (int k = 0; k < 64; k++) {
            float a[4];
#pragma unroll
            for (int i = 0; i < 4; i++) a[i] = Ss[(tr * 4 + i) * 68 + k];
            float4 v4 = *(const float4*)&Vs[k * 68 + tc * 4];
#pragma unroll
            for (int i = 0; i < 4; i++) {
                o[i * 4 + 0] += a[i] * v4.x;
                o[i * 4 + 1] += a[i] * v4.y;
                o[i * 4 + 2] += a[i] * v4.z;
                o[i * 4 + 3] += a[i] * v4.w;
            }
        }
        __syncthreads();
    }

    // Finalize: divide by l, write [B,L,H*DH]
    if (p == 0) Cr[r] = 1.f / l;
    __syncthreads();
#pragma unroll
    for (int i = 0; i < 4; i++) {
        float linv = Cr[tr * 4 + i];
        float4 ov = make_float4(o[i * 4 + 0] * linv, o[i * 4 + 1] * linv,
                                o[i * 4 + 2] * linv, o[i * 4 + 3] * linv);
        *(float4*)(out + ((size_t)(b * L_ + q0 + tr * 4 + i)) * 1024 + h * 64 + tc * 4) = ov;
    }
}

// ---------------------------------------------------------------------------
extern "C" void kernel_launch(void* const* d_in, const int* in_sizes, int n_in,
                              void* d_out, int out_size)
{
    (void)in_sizes; (void)n_in; (void)out_size;
    const float* x      = (const float*)d_in[0];   // [B,L,D]
    const float* w_qkv  = (const float*)d_in[1];   // [3D,D]
    const float* w_proj = (const float*)d_in[2];   // [D,D]
    float* out = (float*)d_out;                    // [B,L,D]

    float* qkvp = nullptr;
    float* attnp = nullptr;
    cudaGetSymbolAddress((void**)&qkvp, g_qkv);
    cudaGetSymbolAddress((void**)&attnp, g_attn);

    const int M = B_ * L_;  // 8192

    // 1) QKV GEMM: [8192,1024] x [3072,1024]^T -> [8192,3072]
    {
        dim3 grid(3 * D_ / 128, M / 128);
        sgemm_nt<<<grid, 256>>>(x, w_qkv, qkvp, M, 3 * D_, D_);
    }

    // 2) Flash attention
    {
        cudaFuncSetAttribute(attn_kernel,
                             cudaFuncAttributeMaxDynamicSharedMemorySize,
                             ATTN_SMEM_BYTES);
        dim3 grid(L_ / 64, H_, B_);
        attn_kernel<<<grid, 256, ATTN_SMEM_BYTES>>>(qkvp, attnp);
    }

    // 3) Output projection: [8192,1024] x [1024,1024]^T -> [8192,1024]
    {
        dim3 grid(D_ / 128, M / 128);
        sgemm_nt<<<grid, 256>>>(attnp, w_proj, out, M, D_, D_);
    }
}

// round 3
// speedup vs baseline: 3.0608x; 3.0601x over previous
#include <cuda_runtime.h>
#include <cstdint>

#define B_ 4
#define L_ 2048
#define D_ 1024
#define H_ 16

// Scratch (device globals; allocation-free per harness rules)
__device__ float g_qkv[B_ * L_ * 3 * D_];   // [B*L, 3072], tf32-rounded
__device__ float g_attn[B_ * L_ * D_];      // [B*L, 1024], raw fp32

// ---------------- helpers ----------------
__device__ __forceinline__ float rna(float x) {
    uint32_t u; asm("cvt.rna.tf32.f32 %0, %1;" : "=r"(u) : "f"(x));
    return __uint_as_float(u);
}
__device__ __forceinline__ float ex2f(float x) {
    float r; asm("ex2.approx.ftz.f32 %0, %1;" : "=f"(r) : "f"(x)); return r;
}
// D += A*B, m16n8k8 tf32 (A row-major, B col-major)
__device__ __forceinline__ void mma8(float* c, const float* a, float b0, float b1) {
    asm volatile(
        "mma.sync.aligned.m16n8k8.row.col.f32.tf32.tf32.f32 "
        "{%0,%1,%2,%3}, {%4,%5,%6,%7}, {%8,%9}, {%0,%1,%2,%3};"
        : "+f"(c[0]), "+f"(c[1]), "+f"(c[2]), "+f"(c[3])
        : "r"(__float_as_uint(a[0])), "r"(__float_as_uint(a[1])),
          "r"(__float_as_uint(a[2])), "r"(__float_as_uint(a[3])),
          "r"(__float_as_uint(b0)), "r"(__float_as_uint(b1)));
}
__device__ __forceinline__ uint32_t sptr(const void* p) {
    uint32_t a;
    asm("{ .reg .u64 t; cvta.to.shared.u64 t, %1; cvt.u32.u64 %0, t; }" : "=r"(a) : "l"(p));
    return a;
}
__device__ __forceinline__ void cp16(uint32_t s, const void* g) {
    asm volatile("cp.async.cg.shared.global [%0], [%1], 16;" :: "r"(s), "l"(g));
}
#define CPC() asm volatile("cp.async.commit_group;" ::: "memory")
#define CPW(n) asm volatile("cp.async.wait_group %0;" :: "n"(n) : "memory")

// ---------------------------------------------------------------------------
// Tensor-core SGEMM (NT): C[m,n] = sum_k A[m,k]*Bm[n,k].
// Block 128x128, 128 threads (4 warps, warp tile 64x64), k-tile 16,
// cp.async double buffer. Operands rna-rounded at fragment load.
// ---------------------------------------------------------------------------
__global__ __launch_bounds__(128)
void gemm_tc(const float* __restrict__ A, const float* __restrict__ Bm,
             float* __restrict__ C, int M, int N, int K, int roundOut)
{
    __shared__ float As[2][128][20];
    __shared__ float Bs[2][128][20];

    const int tid = threadIdx.x, warp = tid >> 5, lane = tid & 31;
    const int g = lane >> 2, tg = lane & 3;
    const int wm0 = (warp >> 1) * 64, wn0 = (warp & 1) * 64;
    const size_t ar0 = (size_t)blockIdx.y * 128, br0 = (size_t)blockIdx.x * 128;

    float acc[4][8][4];
#pragma unroll
    for (int mi = 0; mi < 4; mi++)
#pragma unroll
        for (int ni = 0; ni < 8; ni++)
#pragma unroll
            for (int r = 0; r < 4; r++) acc[mi][ni][r] = 0.f;

    auto stage = [&](int s, int k0) {
#pragma unroll
        for (int i = 0; i < 4; i++) {
            int v = tid + i * 128, row = v >> 2, c = (v & 3) * 4;
            cp16(sptr(&As[s][row][c]), A + (ar0 + row) * (size_t)K + k0 + c);
            cp16(sptr(&Bs[s][row][c]), Bm + (br0 + row) * (size_t)K + k0 + c);
        }
    };

    const int nk = K >> 4;
    stage(0, 0); CPC();

    for (int kt = 0; kt < nk; kt++) {
        CPW(0); __syncthreads();
        if (kt + 1 < nk) { stage((kt + 1) & 1, (kt + 1) * 16); CPC(); }
        const int buf = kt & 1;
#pragma unroll
        for (int ks = 0; ks < 2; ks++) {
            const int k0 = ks * 8;
            float a[4][4];
#pragma unroll
            for (int mi = 0; mi < 4; mi++) {
                int rm = wm0 + mi * 16;
                a[mi][0] = rna(As[buf][rm + g][k0 + tg]);
                a[mi][1] = rna(As[buf][rm + g + 8][k0 + tg]);
                a[mi][2] = rna(As[buf][rm + g][k0 + tg + 4]);
                a[mi][3] = rna(As[buf][rm + g + 8][k0 + tg + 4]);
            }
#pragma unroll
            for (int ni = 0; ni < 8; ni++) {
                int rn = wn0 + ni * 8;
                float b0 = rna(Bs[buf][rn + g][k0 + tg]);
                float b1 = rna(Bs[buf][rn + g][k0 + tg + 4]);
#pragma unroll
                for (int mi = 0; mi < 4; mi++) mma8(acc[mi][ni], a[mi], b0, b1);
            }
        }
    }

#pragma unroll
    for (int mi = 0; mi < 4; mi++) {
#pragma unroll
        for (int ni = 0; ni < 8; ni++) {
            size_t col = br0 + wn0 + ni * 8 + 2 * tg;
            float v0 = acc[mi][ni][0], v1 = acc[mi][ni][1];
            float v2 = acc[mi][ni][2], v3 = acc[mi][ni][3];
            if (roundOut) { v0 = rna(v0); v1 = rna(v1); v2 = rna(v2); v3 = rna(v3); }
            *(float2*)&C[(ar0 + wm0 + mi * 16 + g) * (size_t)N + col] = make_float2(v0, v1);
            *(float2*)&C[(ar0 + wm0 + mi * 16 + g + 8) * (size_t)N + col] = make_float2(v2, v3);
        }
    }
}

// ---------------------------------------------------------------------------
// Tensor-core flash attention. Block = 128 queries x (b,h). 8 warps; warp w
// owns query rows [w*16, w*16+16). Key tiles of 64, cp.async double buffered.
// Q/K/V arrive tf32-rounded (GEMM1 epilogue). Softmax in base-2 domain with
// scale folded into the exp argument. P rna-rounded into per-warp SMEM strip.
// ---------------------------------------------------------------------------
#define QS 76
#define VS 72
#define ATTN_SMEM ((128*QS + 2*64*QS + 2*64*VS + 128*QS) * 4)

__global__ __launch_bounds__(256)
void attn_tc(const float* __restrict__ qkv, float* __restrict__ out)
{
    extern __shared__ float smf[];
    float* Qs  = smf;                  // [128][76]
    float* Ksm = Qs + 128 * QS;        // [2][64][76]
    float* Vsm = Ksm + 2 * 64 * QS;    // [2][64][72]
    float* Ps  = Vsm + 2 * 64 * VS;    // [128][76]

    const int tid = threadIdx.x, warp = tid >> 5, lane = tid & 31;
    const int g = lane >> 2, tg = lane & 3;
    const int rm = warp * 16;
    const int q0 = blockIdx.x * 128, h = blockIdx.y, b = blockIdx.z;
    const float c2s = 0.18033688f;  // 0.125 * log2(e)

    // Load Q tile (pre-rounded tf32)
#pragma unroll
    for (int i = 0; i < 8; i++) {
        int v = tid + i * 256, row = v >> 4, c = (v & 15) * 4;
        *(float4*)&Qs[row * QS + c] =
            *(const float4*)(qkv + ((size_t)(b * L_ + q0 + row)) * 3072 + h * 64 + c);
    }

    auto stage = [&](int s, int kt) {
        const float* base = qkv + ((size_t)(b * L_ + kt * 64)) * 3072 + h * 64;
#pragma unroll
        for (int i = 0; i < 4; i++) {
            int v = tid + i * 256, row = v >> 4, c = (v & 15) * 4;
            cp16(sptr(&Ksm[(s * 64 + row) * QS + c]), base + (size_t)row * 3072 + 1024 + c);
            cp16(sptr(&Vsm[(s * 64 + row) * VS + c]), base + (size_t)row * 3072 + 2048 + c);
        }
    };
    stage(0, 0); CPC();
    __syncthreads();

    // Q fragments (m16 x k64): stay in registers for all key tiles
    float qa[8][4];
#pragma unroll
    for (int kj = 0; kj < 8; kj++) {
        int k0 = kj * 8;
        qa[kj][0] = Qs[(rm + g) * QS + k0 + tg];
        qa[kj][1] = Qs[(rm + g + 8) * QS + k0 + tg];
        qa[kj][2] = Qs[(rm + g) * QS + k0 + tg + 4];
        qa[kj][3] = Qs[(rm + g + 8) * QS + k0 + tg + 4];
    }

    float m0 = -1e30f, m1 = -1e30f, l0 = 0.f, l1 = 0.f;
    float o[8][4];
#pragma unroll
    for (int ni = 0; ni < 8; ni++)
#pragma unroll
        for (int r = 0; r < 4; r++) o[ni][r] = 0.f;

    for (int kt = 0; kt < 32; kt++) {
        CPW(0); __syncthreads();
        if (kt + 1 < 32) { stage((kt + 1) & 1, kt + 1); CPC(); }
        const float* Kb = &Ksm[(kt & 1) * 64 * QS];
        const float* Vb = &Vsm[(kt & 1) * 64 * VS];

        // S = Q K^T  (warp: 16 x 64)
        float s[8][4];
#pragma unroll
        for (int ni = 0; ni < 8; ni++)
#pragma unroll
            for (int r = 0; r < 4; r++) s[ni][r] = 0.f;
#pragma unroll
        for (int kj = 0; kj < 8; kj++) {
            int k0 = kj * 8;
#pragma unroll
            for (int ni = 0; ni < 8; ni++) {
                float b0 = Kb[(ni * 8 + g) * QS + k0 + tg];
                float b1 = Kb[(ni * 8 + g) * QS + k0 + tg + 4];
                mma8(s[ni], qa[kj], b0, b1);
            }
        }

        // Online softmax (rows g and g+8 of warp strip)
        float mx0 = -1e30f, mx1 = -1e30f;
#pragma unroll
        for (int ni = 0; ni < 8; ni++) {
            mx0 = fmaxf(mx0, fmaxf(s[ni][0], s[ni][1]));
            mx1 = fmaxf(mx1, fmaxf(s[ni][2], s[ni][3]));
        }
        mx0 = fmaxf(mx0, __shfl_xor_sync(~0u, mx0, 1));
        mx0 = fmaxf(mx0, __shfl_xor_sync(~0u, mx0, 2));
        mx1 = fmaxf(mx1, __shfl_xor_sync(~0u, mx1, 1));
        mx1 = fmaxf(mx1, __shfl_xor_sync(~0u, mx1, 2));
        float nm0 = fmaxf(m0, mx0 * c2s), nm1 = fmaxf(m1, mx1 * c2s);
        float cr0 = ex2f(m0 - nm0), cr1 = ex2f(m1 - nm1);
        m0 = nm0; m1 = nm1;

        float rs0 = 0.f, rs1 = 0.f;
#pragma unroll
        for (int ni = 0; ni < 8; ni++) {
            float p0 = ex2f(fmaf(s[ni][0], c2s, -nm0));
            float p1 = ex2f(fmaf(s[ni][1], c2s, -nm0));
            float p2 = ex2f(fmaf(s[ni][2], c2s, -nm1));
            float p3 = ex2f(fmaf(s[ni][3], c2s, -nm1));
            rs0 += p0 + p1; rs1 += p2 + p3;
            *(float2*)&Ps[(rm + g) * QS + ni * 8 + 2 * tg] = make_float2(rna(p0), rna(p1));
            *(float2*)&Ps[(rm + g + 8) * QS + ni * 8 + 2 * tg] = make_float2(rna(p2), rna(p3));
        }
        rs0 += __shfl_xor_sync(~0u, rs0, 1); rs0 += __shfl_xor_sync(~0u, rs0, 2);
        rs1 += __shfl_xor_sync(~0u, rs1, 1); rs1 += __shfl_xor_sync(~0u, rs1, 2);
        l0 = l0 * cr0 + rs0; l1 = l1 * cr1 + rs1;
#pragma unroll
        for (int ni = 0; ni < 8; ni++) {
            o[ni][0] *= cr0; o[ni][1] *= cr0; o[ni][2] *= cr1; o[ni][3] *= cr1;
        }
        __syncwarp();

        // O += P V  (warp: 16 x 64, K = 64 keys)
#pragma unroll
        for (int kj = 0; kj < 8; kj++) {
            int k0 = kj * 8;
            float pa[4];
            pa[0] = Ps[(rm + g) * QS + k0 + tg];
            pa[1] = Ps[(rm + g + 8) * QS + k0 + tg];
            pa[2] = Ps[(rm + g) * QS + k0 + tg + 4];
            pa[3] = Ps[(rm + g + 8) * QS + k0 + tg + 4];
#pragma unroll
            for (int ni = 0; ni < 8; ni++) {
                float b0 = Vb[(k0 + tg) * VS + ni * 8 + g];
                float b1 = Vb[(k0 + tg + 4) * VS + ni * 8 + g];
                mma8(o[ni], pa, b0, b1);
            }
        }
        __syncwarp();  // PV reads done before next iter's P stores
    }

    float li0 = 1.f / l0, li1 = 1.f / l1;
#pragma unroll
    for (int ni = 0; ni < 8; ni++) {
        size_t c = (size_t)h * 64 + ni * 8 + 2 * tg;
        *(float2*)&out[((size_t)(b * L_ + q0 + rm + g)) * 1024 + c] =
            make_float2(o[ni][0] * li0, o[ni][1] * li0);
        *(float2*)&out[((size_t)(b * L_ + q0 + rm + g + 8)) * 1024 + c] =
            make_float2(o[ni][2] * li1, o[ni][3] * li1);
    }
}

// ---------------------------------------------------------------------------
extern "C" void kernel_launch(void* const* d_in, const int* in_sizes, int n_in,
                              void* d_out, int out_size)
{
    (void)in_sizes; (void)n_in; (void)out_size;
    const float* x      = (const float*)d_in[0];
    const float* w_qkv  = (const float*)d_in[1];
    const float* w_proj = (const float*)d_in[2];
    float* out = (float*)d_out;

    float *qkvp = nullptr, *attnp = nullptr;
    cudaGetSymbolAddress((void**)&qkvp, g_qkv);
    cudaGetSymbolAddress((void**)&attnp, g_attn);

    const int M = B_ * L_;  // 8192

    // 1) QKV GEMM (tf32-rounded epilogue)
    gemm_tc<<<dim3(3 * D_ / 128, M / 128), 128>>>(x, w_qkv, qkvp, M, 3 * D_, D_, 1);

    // 2) Flash attention
    cudaFuncSetAttribute(attn_tc, cudaFuncAttributeMaxDynamicSharedMemorySize, ATTN_SMEM);
    attn_tc<<<dim3(L_ / 128, H_, B_), 256, ATTN_SMEM>>>(qkvp, attnp);

    // 3) Output projection (full fp32 output)
    gemm_tc<<<dim3(D_ / 128, M / 128), 128>>>(attnp, w_proj, out, M, D_, D_, 0);
}